// round 3
// baseline (speedup 1.0000x reference)
#include <cuda_runtime.h>
#include <math.h>

// Problem constants (fixed by the reference setup)
#define N_USER 60000
#define N_ITEM 40000
#define NN     (N_USER + N_ITEM)   // 100000 nodes
#define D      64
#define EMAX   800000
#define NB_SCAN ((NN + 1023) / 1024)   // 98 blocks

// ---- static device scratch (no allocations allowed) ----
__device__ float g_embA[NN * D];
__device__ float g_embB[NN * D];
__device__ float g_light[NN * D];
__device__ float g_rnorm[NN];    // reciprocal norms
__device__ float g_rowsum[NN];   // reciprocal L1 rowsums (1 if rowsum<=0)
__device__ float g_cos[EMAX];
__device__ float g_mem[EMAX];
__device__ float g_aval[EMAX];
__device__ int   g_col[EMAX];
__device__ int   g_rowptr[NN + 1];
__device__ int   g_deg[NN];
__device__ int   g_bsum[128];

// ---------------- CSR build ----------------

__global__ void k_zero_deg() {
    int i = blockIdx.x * blockDim.x + threadIdx.x;
    if (i < NN) g_deg[i] = 0;
}

__global__ void k_hist(const int* __restrict__ src, int E) {
    for (int e = blockIdx.x * blockDim.x + threadIdx.x; e < E;
         e += gridDim.x * blockDim.x)
        atomicAdd(&g_deg[src[e]], 1);
}

__global__ void k_scanA() {
    __shared__ int wsum[32];
    int i = blockIdx.x * 1024 + threadIdx.x;
    int lane = threadIdx.x & 31, wid = threadIdx.x >> 5;
    int v = (i < NN) ? g_deg[i] : 0;
    int x = v;
    #pragma unroll
    for (int o = 1; o < 32; o <<= 1) {
        int y = __shfl_up_sync(0xffffffffu, x, o);
        if (lane >= o) x += y;
    }
    if (lane == 31) wsum[wid] = x;
    __syncthreads();
    if (wid == 0) {
        int s = wsum[lane];
        #pragma unroll
        for (int o = 1; o < 32; o <<= 1) {
            int y = __shfl_up_sync(0xffffffffu, s, o);
            if (lane >= o) s += y;
        }
        wsum[lane] = s;
    }
    __syncthreads();
    int woff = (wid > 0) ? wsum[wid - 1] : 0;
    int incl = x + woff;
    if (i < NN) g_rowptr[i] = incl - v;  // exclusive, local to block
    if (threadIdx.x == 1023) g_bsum[blockIdx.x] = incl;
}

__global__ void k_scanB(int nb) {
    int i = threadIdx.x;
    int v = (i < nb) ? g_bsum[i] : 0;
    int x = v;
    #pragma unroll
    for (int o = 1; o < 32; o <<= 1) {
        int y = __shfl_up_sync(0xffffffffu, x, o);
        if ((i & 31) >= o) x += y;
    }
    __shared__ int ws[4];
    if ((i & 31) == 31) ws[i >> 5] = x;
    __syncthreads();
    int off = 0;
    for (int w = 0; w < (i >> 5); w++) off += ws[w];
    if (i < nb) g_bsum[i] = x - v + off;  // exclusive
}

__global__ void k_scanC(int E) {
    int i = blockIdx.x * 1024 + threadIdx.x;
    if (i < NN) {
        g_rowptr[i] += g_bsum[blockIdx.x];
        g_deg[i] = 0;  // reset as scatter cursor
    }
    if (i == 0) g_rowptr[NN] = E;
}

__global__ void k_scatter(const int* __restrict__ src, const int* __restrict__ dst,
                          const float* __restrict__ adj, int E) {
    for (int e = blockIdx.x * blockDim.x + threadIdx.x; e < E;
         e += gridDim.x * blockDim.x) {
        int r = src[e];
        int pos = g_rowptr[r] + atomicAdd(&g_deg[r], 1);
        g_col[pos]  = dst[e];
        float a = adj[e];
        g_aval[pos] = a;
        g_mem[pos]  = a;   // memory starts as adjacency values
    }
}

// ---------------- init embeddings ----------------

__global__ void k_init_emb(const float* __restrict__ ue, const float* __restrict__ ie) {
    for (int i = blockIdx.x * blockDim.x + threadIdx.x; i < NN * D;
         i += gridDim.x * blockDim.x) {
        float v = (i < N_USER * D) ? ue[i] : ie[i - N_USER * D];
        g_embA[i]  = v;
        g_light[i] = v;   // embs[0] contribution to the mean-sum
    }
}

// reciprocal norms of g_embA (layer-0 input only; later layers fused in k_spmm)
__global__ void k_rnorm0() {
    int row = blockIdx.x * (blockDim.x >> 5) + (threadIdx.x >> 5);
    if (row >= NN) return;
    int lane = threadIdx.x & 31;
    float2 v = *(const float2*)(g_embA + row * D + lane * 2);
    float s = v.x * v.x + v.y * v.y;
    #pragma unroll
    for (int o = 16; o; o >>= 1) s += __shfl_xor_sync(0xffffffffu, s, o);
    if (lane == 0) g_rnorm[row] = (s > 1e-24f) ? rsqrtf(s) : 0.f;
}

// ---------------- per-layer edge passes ----------------
// Warp per row; 8 edge-groups of 4 lanes; each lane holds 16 dims (4x float4).

__global__ __launch_bounds__(256) void k_cos(int cur) {
    const float* __restrict__ emb = cur ? g_embB : g_embA;
    int row = blockIdx.x * 8 + (threadIdx.x >> 5);
    if (row >= NN) return;
    int lane = threadIdx.x & 31;
    int g = lane >> 2, sl = lane & 3;

    const float* rp = emb + row * D + sl * 16;
    float4 e0 = *(const float4*)(rp);
    float4 e1 = *(const float4*)(rp + 4);
    float4 e2 = *(const float4*)(rp + 8);
    float4 e3 = *(const float4*)(rp + 12);
    float rn_r = g_rnorm[row];

    int beg = g_rowptr[row], end = g_rowptr[row + 1];
    int nit = (end - beg + 7) >> 3;
    float rs = 0.f;
    for (int it = 0; it < nit; it++) {
        int pos = beg + it * 8 + g;
        bool act = pos < end;
        int c = act ? g_col[pos] : row;
        const float* cp = emb + c * D + sl * 16;
        float4 d0 = *(const float4*)(cp);
        float4 d1 = *(const float4*)(cp + 4);
        float4 d2 = *(const float4*)(cp + 8);
        float4 d3 = *(const float4*)(cp + 12);
        float p = e0.x * d0.x + e0.y * d0.y + e0.z * d0.z + e0.w * d0.w
                + e1.x * d1.x + e1.y * d1.y + e1.z * d1.z + e1.w * d1.w
                + e2.x * d2.x + e2.y * d2.y + e2.z * d2.z + e2.w * d2.w
                + e3.x * d3.x + e3.y * d3.y + e3.z * d3.z + e3.w * d3.w;
        p += __shfl_xor_sync(0xffffffffu, p, 1);
        p += __shfl_xor_sync(0xffffffffu, p, 2);
        float cs = p * rn_r * g_rnorm[c];
        if (!act) cs = 0.f;
        if (act && sl == 0) g_cos[pos] = cs;
        rs += fabsf(cs);
    }
    // rs identical across the 4 lanes of a group; combine the 8 groups
    rs += __shfl_xor_sync(0xffffffffu, rs, 4);
    rs += __shfl_xor_sync(0xffffffffu, rs, 8);
    rs += __shfl_xor_sync(0xffffffffu, rs, 16);
    // store reciprocal directly (reference divides by rowsum iff > 0, else by 1)
    if (lane == 0) g_rowsum[row] = (rs > 0.f) ? 1.f / rs : 1.f;
}

// coef -> prune -> mem EMA -> SpMM row accumulate (+ light sum, + next rnorm)
__global__ __launch_bounds__(256) void k_spmm(int cur, int last,
                                              const float* __restrict__ W,
                                              const float* __restrict__ B) {
    const float* __restrict__ embin = cur ? g_embB : g_embA;
    float* embout                   = cur ? g_embA : g_embB;
    int row = blockIdx.x * 8 + (threadIdx.x >> 5);
    if (row >= NN) return;
    int lane = threadIdx.x & 31;
    int g = lane >> 2, sl = lane & 3;

    float w0 = W[0], w1 = W[1], bb = B[0];
    float invr = g_rowsum[row];   // already reciprocal
    int beg = g_rowptr[row], end = g_rowptr[row + 1];
    int nit = (end - beg + 7) >> 3;

    float acc[16];
    #pragma unroll
    for (int k = 0; k < 16; k++) acc[k] = 0.f;

    for (int it = 0; it < nit; it++) {
        int pos = beg + it * 8 + g;
        bool act = pos < end;
        int posc = act ? pos : beg;
        int c = g_col[posc];
        float cs = g_cos[posc];
        float c1 = cs * invr;
        float c2 = cs * g_rowsum[c];               // cos symmetric: coef[rev] = cs / rowsum[dst]
        float z = w0 * c1 + w1 * c2 + bb;          // sigmoid(z)>0.5 <=> z>0
        float coef = (z > 0.f) ? c1 : 0.f;
        float m = 0.5f * (g_mem[posc] + coef);
        if (act && sl == 0) g_mem[pos] = m;
        float gv = act ? m * g_aval[posc] : 0.f;
        const float* cp = embin + c * D + sl * 16;
        float4 d0 = *(const float4*)(cp);
        float4 d1 = *(const float4*)(cp + 4);
        float4 d2 = *(const float4*)(cp + 8);
        float4 d3 = *(const float4*)(cp + 12);
        acc[0]  += gv * d0.x; acc[1]  += gv * d0.y; acc[2]  += gv * d0.z; acc[3]  += gv * d0.w;
        acc[4]  += gv * d1.x; acc[5]  += gv * d1.y; acc[6]  += gv * d1.z; acc[7]  += gv * d1.w;
        acc[8]  += gv * d2.x; acc[9]  += gv * d2.y; acc[10] += gv * d2.z; acc[11] += gv * d2.w;
        acc[12] += gv * d3.x; acc[13] += gv * d3.y; acc[14] += gv * d3.z; acc[15] += gv * d3.w;
    }
    // combine the 8 groups (same dims live in lanes sl, sl+4, ..., sl+28)
    #pragma unroll
    for (int o = 4; o <= 16; o <<= 1) {
        #pragma unroll
        for (int k = 0; k < 16; k++)
            acc[k] += __shfl_xor_sync(0xffffffffu, acc[k], o);
    }
    if (g == 0) {
        // light accumulation
        float* lp = g_light + row * D + sl * 16;
        #pragma unroll
        for (int q = 0; q < 4; q++) {
            float4 lv = *(float4*)(lp + q * 4);
            lv.x += acc[q * 4 + 0]; lv.y += acc[q * 4 + 1];
            lv.z += acc[q * 4 + 2]; lv.w += acc[q * 4 + 3];
            *(float4*)(lp + q * 4) = lv;
        }
        if (!last) {
            float* op = embout + row * D + sl * 16;
            #pragma unroll
            for (int q = 0; q < 4; q++)
                *(float4*)(op + q * 4) = make_float4(acc[q * 4 + 0], acc[q * 4 + 1],
                                                     acc[q * 4 + 2], acc[q * 4 + 3]);
            // fused reciprocal norm of the output row (input of next layer's cos)
            float ss = 0.f;
            #pragma unroll
            for (int k = 0; k < 16; k++) ss += acc[k] * acc[k];
            ss += __shfl_xor_sync(0xffffffffu, ss, 1);
            ss += __shfl_xor_sync(0xffffffffu, ss, 2);
            if (sl == 0) g_rnorm[row] = (ss > 1e-24f) ? rsqrtf(ss) : 0.f;
        }
    }
}

// ---------------- final: fused gather + sigmoid GEMM ----------------

__global__ void k_gemm(const int* __restrict__ users, const int* __restrict__ items,
                       float* __restrict__ out, int Bu, int Bi) {
    __shared__ float As[64][65];
    __shared__ float Bs[64][65];
    int tx = threadIdx.x, ty = threadIdx.y;       // 16x16
    int t = ty * 16 + tx;
    int rowBase = blockIdx.y * 64, colBase = blockIdx.x * 64;
    #pragma unroll
    for (int i = 0; i < 4; i++) {
        int j = t + i * 256;       // float4 slot 0..1023
        int r = j >> 4;
        int kq = (j & 15) * 4;
        float4 a = make_float4(0, 0, 0, 0);
        if (rowBase + r < Bu) {
            int u = users[rowBase + r];
            float4 v = *(const float4*)(g_light + u * D + kq);
            a = make_float4(0.25f * v.x, 0.25f * v.y, 0.25f * v.z, 0.25f * v.w);
        }
        As[r][kq] = a.x; As[r][kq + 1] = a.y; As[r][kq + 2] = a.z; As[r][kq + 3] = a.w;
        float4 b = make_float4(0, 0, 0, 0);
        if (colBase + r < Bi) {
            int itm = items[colBase + r];
            float4 v = *(const float4*)(g_light + (N_USER + itm) * D + kq);
            b = make_float4(0.25f * v.x, 0.25f * v.y, 0.25f * v.z, 0.25f * v.w);
        }
        Bs[r][kq] = b.x; Bs[r][kq + 1] = b.y; Bs[r][kq + 2] = b.z; Bs[r][kq + 3] = b.w;
    }
    __syncthreads();
    float acc[4][4] = {};
    #pragma unroll
    for (int k = 0; k < 64; k++) {
        float a0 = As[ty * 4 + 0][k], a1 = As[ty * 4 + 1][k];
        float a2 = As[ty * 4 + 2][k], a3 = As[ty * 4 + 3][k];
        float b0 = Bs[tx * 4 + 0][k], b1 = Bs[tx * 4 + 1][k];
        float b2 = Bs[tx * 4 + 2][k], b3 = Bs[tx * 4 + 3][k];
        acc[0][0] += a0 * b0; acc[0][1] += a0 * b1; acc[0][2] += a0 * b2; acc[0][3] += a0 * b3;
        acc[1][0] += a1 * b0; acc[1][1] += a1 * b1; acc[1][2] += a1 * b2; acc[1][3] += a1 * b3;
        acc[2][0] += a2 * b0; acc[2][1] += a2 * b1; acc[2][2] += a2 * b2; acc[2][3] += a2 * b3;
        acc[3][0] += a3 * b0; acc[3][1] += a3 * b1; acc[3][2] += a3 * b2; acc[3][3] += a3 * b3;
    }
    #pragma unroll
    for (int i = 0; i < 4; i++)
        #pragma unroll
        for (int j = 0; j < 4; j++) {
            int r = rowBase + ty * 4 + i;
            int c = colBase + tx * 4 + j;
            if (r < Bu && c < Bi)
                out[r * Bi + c] = 1.f / (1.f + __expf(-acc[i][j]));
        }
}

// ---------------- launch ----------------

extern "C" void kernel_launch(void* const* d_in, const int* in_sizes, int n_in,
                              void* d_out, int out_size) {
    const int*   users    = (const int*)d_in[0];
    const int*   items    = (const int*)d_in[1];
    const float* user_emb = (const float*)d_in[2];
    const float* item_emb = (const float*)d_in[3];
    const float* W_prune  = (const float*)d_in[4];
    const float* b_prune  = (const float*)d_in[5];
    const int*   src      = (const int*)d_in[6];
    const int*   dst      = (const int*)d_in[7];
    // d_in[8] = rev_perm (unused: cosine is symmetric)
    const float* adj_vals = (const float*)d_in[9];

    int Bu = in_sizes[0];
    int Bi = in_sizes[1];
    int E  = in_sizes[6];

    float* out = (float*)d_out;

    int ebl = (E + 1023) / 1024;

    // CSR build
    k_zero_deg<<<NB_SCAN, 1024>>>();
    k_hist<<<ebl, 1024>>>(src, E);
    k_scanA<<<NB_SCAN, 1024>>>();
    k_scanB<<<1, 128>>>(NB_SCAN);
    k_scanC<<<NB_SCAN, 1024>>>(E);
    k_scatter<<<ebl, 1024>>>(src, dst, adj_vals, E);

    // init embeddings + light accumulator + layer-0 reciprocal norms
    k_init_emb<<<(NN * D + 1023) / 1024, 1024>>>(user_emb, item_emb);
    k_rnorm0<<<(NN + 7) / 8, 256>>>();

    // 3 propagation layers (warp per node row, 8-edge groups)
    int rowsblocks = (NN + 7) / 8;   // 8 warps per 256-thread block
    for (int l = 0; l < 3; l++) {
        int cur = l & 1;
        k_cos<<<rowsblocks, 256>>>(cur);
        k_spmm<<<rowsblocks, 256>>>(cur, l == 2, W_prune, b_prune);
    }

    // fused gather + sigmoid GEMM
    dim3 gblk(16, 16);
    dim3 ggrd((Bi + 63) / 64, (Bu + 63) / 64);
    k_gemm<<<ggrd, gblk>>>(users, items, out, Bu, Bi);
}

// round 4
// speedup vs baseline: 1.4980x; 1.4980x over previous
#include <cuda_runtime.h>
#include <math.h>

// Problem constants (fixed by the reference setup)
#define N_USER 60000
#define N_ITEM 40000
#define NN     (N_USER + N_ITEM)   // 100000 nodes
#define D      64
#define EMAX   800000
#define NB_SCAN ((NN + 1023) / 1024)   // 98 blocks

// ---- static device scratch (no allocations allowed) ----
__device__ float  g_embA[NN * D];
__device__ float  g_embB[NN * D];
__device__ float  g_light[NN * D];
__device__ float  g_rnorm[NN];    // reciprocal norms
__device__ float  g_rowsum[NN];   // reciprocal L1 rowsums (1 if rowsum<=0)
__device__ float4 g_edge[EMAX];   // {col(bits), cos, mem, aval}
__device__ int    g_col[EMAX];
__device__ int    g_rowptr[NN + 1];
__device__ int    g_deg[NN];
__device__ int    g_bsum[128];

// ---------------- CSR build ----------------

__global__ void k_hist(const int* __restrict__ src, int E) {
    for (int e = blockIdx.x * blockDim.x + threadIdx.x; e < E;
         e += gridDim.x * blockDim.x)
        atomicAdd(&g_deg[src[e]], 1);
}

__global__ void k_scanA() {
    __shared__ int wsum[32];
    int i = blockIdx.x * 1024 + threadIdx.x;
    int lane = threadIdx.x & 31, wid = threadIdx.x >> 5;
    int v = (i < NN) ? g_deg[i] : 0;
    int x = v;
    #pragma unroll
    for (int o = 1; o < 32; o <<= 1) {
        int y = __shfl_up_sync(0xffffffffu, x, o);
        if (lane >= o) x += y;
    }
    if (lane == 31) wsum[wid] = x;
    __syncthreads();
    if (wid == 0) {
        int s = wsum[lane];
        #pragma unroll
        for (int o = 1; o < 32; o <<= 1) {
            int y = __shfl_up_sync(0xffffffffu, s, o);
            if (lane >= o) s += y;
        }
        wsum[lane] = s;
    }
    __syncthreads();
    int woff = (wid > 0) ? wsum[wid - 1] : 0;
    int incl = x + woff;
    if (i < NN) g_rowptr[i] = incl - v;  // exclusive, local to block
    if (threadIdx.x == 1023) g_bsum[blockIdx.x] = incl;
}

__global__ void k_scanB(int nb) {
    int i = threadIdx.x;
    int v = (i < nb) ? g_bsum[i] : 0;
    int x = v;
    #pragma unroll
    for (int o = 1; o < 32; o <<= 1) {
        int y = __shfl_up_sync(0xffffffffu, x, o);
        if ((i & 31) >= o) x += y;
    }
    __shared__ int ws[4];
    if ((i & 31) == 31) ws[i >> 5] = x;
    __syncthreads();
    int off = 0;
    for (int w = 0; w < (i >> 5); w++) off += ws[w];
    if (i < nb) g_bsum[i] = x - v + off;  // exclusive
}

__global__ void k_scanC(int E) {
    int i = blockIdx.x * 1024 + threadIdx.x;
    if (i < NN) {
        g_rowptr[i] += g_bsum[blockIdx.x];
        g_deg[i] = 0;  // reset as scatter cursor
    }
    if (i == 0) g_rowptr[NN] = E;
}

__global__ void k_scatter(const int* __restrict__ src, const int* __restrict__ dst,
                          const float* __restrict__ adj, int E) {
    for (int e = blockIdx.x * blockDim.x + threadIdx.x; e < E;
         e += gridDim.x * blockDim.x) {
        int r = src[e];
        int pos = g_rowptr[r] + atomicAdd(&g_deg[r], 1);
        int c = dst[e];
        float a = adj[e];
        g_col[pos]  = c;
        g_edge[pos] = make_float4(__int_as_float(c), 0.f, a, a); // {col, cos, mem=a, aval=a}
    }
}

// ---------------- init embeddings + light + layer-0 rnorm (fused) ----------------

__global__ void k_init(const float* __restrict__ ue, const float* __restrict__ ie) {
    int row = blockIdx.x * (blockDim.x >> 5) + (threadIdx.x >> 5);
    if (row >= NN) return;
    int lane = threadIdx.x & 31;
    const float* srcp = (row < N_USER) ? (ue + row * D) : (ie + (row - N_USER) * D);
    float2 v = *(const float2*)(srcp + lane * 2);
    *(float2*)(g_embA + row * D + lane * 2)  = v;
    *(float2*)(g_light + row * D + lane * 2) = v;
    float s = v.x * v.x + v.y * v.y;
    #pragma unroll
    for (int o = 16; o; o >>= 1) s += __shfl_xor_sync(0xffffffffu, s, o);
    if (lane == 0) g_rnorm[row] = (s > 1e-24f) ? rsqrtf(s) : 0.f;
}

// ---------------- per-layer edge passes ----------------
// Warp per row; 4 edge-groups of 8 lanes; each lane holds 8 dims (2x float4).

__global__ __launch_bounds__(256) void k_cos(int cur) {
    const float* __restrict__ emb = cur ? g_embB : g_embA;
    int row = blockIdx.x * 8 + (threadIdx.x >> 5);
    if (row >= NN) return;
    int lane = threadIdx.x & 31;
    int g = lane >> 3, sl = lane & 7;

    const float* rp = emb + row * D + sl * 8;
    float4 e0 = *(const float4*)(rp);
    float4 e1 = *(const float4*)(rp + 4);
    float rn_r = g_rnorm[row];

    int beg = g_rowptr[row], end = g_rowptr[row + 1];
    int nit = (end - beg + 3) >> 2;

    // prefetch first column for this group
    int pos = beg + g;
    bool actn = pos < end;
    int cnext = actn ? g_col[pos] : 0;

    float rs = 0.f;
    for (int it = 0; it < nit; it++) {
        bool act = actn;
        int c = cnext;
        int curpos = pos;
        pos += 4;
        actn = pos < end;
        if (actn) cnext = g_col[pos];     // prefetch next iteration's column

        float p = 0.f;
        float rn_c = 0.f;
        if (act) {
            const float* cp = emb + c * D + sl * 8;
            float4 d0 = *(const float4*)(cp);
            float4 d1 = *(const float4*)(cp + 4);
            rn_c = g_rnorm[c];
            p = e0.x * d0.x + e0.y * d0.y + e0.z * d0.z + e0.w * d0.w
              + e1.x * d1.x + e1.y * d1.y + e1.z * d1.z + e1.w * d1.w;
        }
        p += __shfl_xor_sync(0xffffffffu, p, 1);
        p += __shfl_xor_sync(0xffffffffu, p, 2);
        p += __shfl_xor_sync(0xffffffffu, p, 4);
        float cs = p * rn_r * rn_c;        // 0 for inactive (rn_c = 0)
        if (act && sl == 0) ((float*)(g_edge + curpos))[1] = cs;
        rs += fabsf(cs);
    }
    // rs identical across the 8 lanes of a group; combine the 4 groups
    rs += __shfl_xor_sync(0xffffffffu, rs, 8);
    rs += __shfl_xor_sync(0xffffffffu, rs, 16);
    // store reciprocal directly (reference divides by rowsum iff > 0, else by 1)
    if (lane == 0) g_rowsum[row] = (rs > 0.f) ? 1.f / rs : 1.f;
}

// coef -> prune -> mem EMA -> SpMM row accumulate (+ light sum, + next rnorm)
__global__ __launch_bounds__(256) void k_spmm(int cur, int last,
                                              const float* __restrict__ W,
                                              const float* __restrict__ B) {
    const float* __restrict__ embin = cur ? g_embB : g_embA;
    float* embout                   = cur ? g_embA : g_embB;
    int row = blockIdx.x * 8 + (threadIdx.x >> 5);
    if (row >= NN) return;
    int lane = threadIdx.x & 31;
    int g = lane >> 3, sl = lane & 7;

    float w0 = W[0], w1 = W[1], bb = B[0];
    float invr = g_rowsum[row];   // already reciprocal
    int beg = g_rowptr[row], end = g_rowptr[row + 1];
    int nit = (end - beg + 3) >> 2;

    // prefetch first edge record
    int pos = beg + g;
    bool actn = pos < end;
    float4 en = actn ? g_edge[pos] : make_float4(0, 0, 0, 0);

    float a0 = 0.f, a1 = 0.f, a2 = 0.f, a3 = 0.f;
    float a4 = 0.f, a5 = 0.f, a6 = 0.f, a7 = 0.f;
    for (int it = 0; it < nit; it++) {
        bool act = actn;
        float4 er = en;
        int curpos = pos;
        pos += 4;
        actn = pos < end;
        if (actn) en = g_edge[pos];       // prefetch next edge record

        if (act) {
            int c = __float_as_int(er.x);
            float cs = er.y;
            float c1 = cs * invr;
            float c2 = cs * g_rowsum[c];           // cos symmetric: coef[rev] = cs / rowsum[dst]
            float z = w0 * c1 + w1 * c2 + bb;      // sigmoid(z)>0.5 <=> z>0
            float coef = (z > 0.f) ? c1 : 0.f;
            float m = 0.5f * (er.z + coef);
            if (!last && sl == 0) ((float*)(g_edge + curpos))[2] = m;
            float gv = m * er.w;
            const float* cp = embin + c * D + sl * 8;
            float4 d0 = *(const float4*)(cp);
            float4 d1 = *(const float4*)(cp + 4);
            a0 += gv * d0.x; a1 += gv * d0.y; a2 += gv * d0.z; a3 += gv * d0.w;
            a4 += gv * d1.x; a5 += gv * d1.y; a6 += gv * d1.z; a7 += gv * d1.w;
        }
    }
    // combine the 4 groups (same dims live in lanes sl, sl+8, sl+16, sl+24)
    #pragma unroll
    for (int o = 8; o <= 16; o <<= 1) {
        a0 += __shfl_xor_sync(0xffffffffu, a0, o);
        a1 += __shfl_xor_sync(0xffffffffu, a1, o);
        a2 += __shfl_xor_sync(0xffffffffu, a2, o);
        a3 += __shfl_xor_sync(0xffffffffu, a3, o);
        a4 += __shfl_xor_sync(0xffffffffu, a4, o);
        a5 += __shfl_xor_sync(0xffffffffu, a5, o);
        a6 += __shfl_xor_sync(0xffffffffu, a6, o);
        a7 += __shfl_xor_sync(0xffffffffu, a7, o);
    }
    // after the xor-combine every lane holds the full sums for its 8 dims
    if (g == 0) {
        float* lp = g_light + row * D + sl * 8;
        float4 l0 = *(float4*)(lp);
        float4 l1 = *(float4*)(lp + 4);
        l0.x += a0; l0.y += a1; l0.z += a2; l0.w += a3;
        l1.x += a4; l1.y += a5; l1.z += a6; l1.w += a7;
        *(float4*)(lp)     = l0;
        *(float4*)(lp + 4) = l1;
    }
    if (!last) {
        // fused reciprocal norm of the output row (input of next layer's cos)
        float ss = a0 * a0 + a1 * a1 + a2 * a2 + a3 * a3
                 + a4 * a4 + a5 * a5 + a6 * a6 + a7 * a7;
        ss += __shfl_xor_sync(0xffffffffu, ss, 1);
        ss += __shfl_xor_sync(0xffffffffu, ss, 2);
        ss += __shfl_xor_sync(0xffffffffu, ss, 4);
        if (g == 0) {
            float* op = embout + row * D + sl * 8;
            *(float4*)(op)     = make_float4(a0, a1, a2, a3);
            *(float4*)(op + 4) = make_float4(a4, a5, a6, a7);
            if (sl == 0) g_rnorm[row] = (ss > 1e-24f) ? rsqrtf(ss) : 0.f;
        }
    }
}

// ---------------- final: fused gather + sigmoid GEMM ----------------

__global__ void k_gemm(const int* __restrict__ users, const int* __restrict__ items,
                       float* __restrict__ out, int Bu, int Bi) {
    __shared__ float As[64][65];
    __shared__ float Bs[64][65];
    int tx = threadIdx.x, ty = threadIdx.y;       // 16x16
    int t = ty * 16 + tx;
    int rowBase = blockIdx.y * 64, colBase = blockIdx.x * 64;
    #pragma unroll
    for (int i = 0; i < 4; i++) {
        int j = t + i * 256;       // float4 slot 0..1023
        int r = j >> 4;
        int kq = (j & 15) * 4;
        float4 a = make_float4(0, 0, 0, 0);
        if (rowBase + r < Bu) {
            int u = users[rowBase + r];
            float4 v = *(const float4*)(g_light + u * D + kq);
            a = make_float4(0.25f * v.x, 0.25f * v.y, 0.25f * v.z, 0.25f * v.w);
        }
        As[r][kq] = a.x; As[r][kq + 1] = a.y; As[r][kq + 2] = a.z; As[r][kq + 3] = a.w;
        float4 b = make_float4(0, 0, 0, 0);
        if (colBase + r < Bi) {
            int itm = items[colBase + r];
            float4 v = *(const float4*)(g_light + (N_USER + itm) * D + kq);
            b = make_float4(0.25f * v.x, 0.25f * v.y, 0.25f * v.z, 0.25f * v.w);
        }
        Bs[r][kq] = b.x; Bs[r][kq + 1] = b.y; Bs[r][kq + 2] = b.z; Bs[r][kq + 3] = b.w;
    }
    __syncthreads();
    float acc[4][4] = {};
    #pragma unroll
    for (int k = 0; k < 64; k++) {
        float a0 = As[ty * 4 + 0][k], a1 = As[ty * 4 + 1][k];
        float a2 = As[ty * 4 + 2][k], a3 = As[ty * 4 + 3][k];
        float b0 = Bs[tx * 4 + 0][k], b1 = Bs[tx * 4 + 1][k];
        float b2 = Bs[tx * 4 + 2][k], b3 = Bs[tx * 4 + 3][k];
        acc[0][0] += a0 * b0; acc[0][1] += a0 * b1; acc[0][2] += a0 * b2; acc[0][3] += a0 * b3;
        acc[1][0] += a1 * b0; acc[1][1] += a1 * b1; acc[1][2] += a1 * b2; acc[1][3] += a1 * b3;
        acc[2][0] += a2 * b0; acc[2][1] += a2 * b1; acc[2][2] += a2 * b2; acc[2][3] += a2 * b3;
        acc[3][0] += a3 * b0; acc[3][1] += a3 * b1; acc[3][2] += a3 * b2; acc[3][3] += a3 * b3;
    }
    #pragma unroll
    for (int i = 0; i < 4; i++)
        #pragma unroll
        for (int j = 0; j < 4; j++) {
            int r = rowBase + ty * 4 + i;
            int c = colBase + tx * 4 + j;
            if (r < Bu && c < Bi)
                out[r * Bi + c] = 1.f / (1.f + __expf(-acc[i][j]));
        }
}

// ---------------- launch ----------------

extern "C" void kernel_launch(void* const* d_in, const int* in_sizes, int n_in,
                              void* d_out, int out_size) {
    const int*   users    = (const int*)d_in[0];
    const int*   items    = (const int*)d_in[1];
    const float* user_emb = (const float*)d_in[2];
    const float* item_emb = (const float*)d_in[3];
    const float* W_prune  = (const float*)d_in[4];
    const float* b_prune  = (const float*)d_in[5];
    const int*   src      = (const int*)d_in[6];
    const int*   dst      = (const int*)d_in[7];
    // d_in[8] = rev_perm (unused: cosine is symmetric)
    const float* adj_vals = (const float*)d_in[9];

    int Bu = in_sizes[0];
    int Bi = in_sizes[1];
    int E  = in_sizes[6];

    float* out = (float*)d_out;

    int ebl = (E + 1023) / 1024;

    // zero degree counters (memset node, not a kernel)
    void* degp = nullptr;
    cudaGetSymbolAddress(&degp, g_deg);
    cudaMemsetAsync(degp, 0, NN * sizeof(int));

    // CSR build
    k_hist<<<ebl, 1024>>>(src, E);
    k_scanA<<<NB_SCAN, 1024>>>();
    k_scanB<<<1, 128>>>(NB_SCAN);
    k_scanC<<<NB_SCAN, 1024>>>(E);
    k_scatter<<<ebl, 1024>>>(src, dst, adj_vals, E);

    // init embeddings + light + layer-0 reciprocal norms (fused, warp per row)
    k_init<<<(NN + 7) / 8, 256>>>(user_emb, item_emb);

    // 3 propagation layers (warp per node row, 4-edge groups, pipelined)
    int rowsblocks = (NN + 7) / 8;   // 8 warps per 256-thread block
    for (int l = 0; l < 3; l++) {
        int cur = l & 1;
        k_cos<<<rowsblocks, 256>>>(cur);
        k_spmm<<<rowsblocks, 256>>>(cur, l == 2, W_prune, b_prune);
    }

    // fused gather + sigmoid GEMM
    dim3 gblk(16, 16);
    dim3 ggrd((Bi + 63) / 64, (Bu + 63) / 64);
    k_gemm<<<ggrd, gblk>>>(users, items, out, Bu, Bi);
}

// round 5
// speedup vs baseline: 1.5913x; 1.0623x over previous
#include <cuda_runtime.h>
#include <math.h>

// Problem constants (fixed by the reference setup)
#define N_USER 60000
#define N_ITEM 40000
#define NN     (N_USER + N_ITEM)   // 100000 nodes
#define D      64
#define EMAX   800000
#define EHALF  (EMAX / 2)
#define NB_SCAN ((NN + 1023) / 1024)   // 98 blocks

// ---- static device scratch (no allocations allowed) ----
__device__ float  g_embA[NN * D];
__device__ float  g_embB[NN * D];
__device__ float  g_light[NN * D];
__device__ float  g_rnorm[NN];    // reciprocal norms
__device__ float  g_rowsum[NN];   // reciprocal L1 rowsums (1 if rowsum<=0)
__device__ float4 g_edge[EMAX];   // {col(bits), cos, mem, aval}
__device__ int2   g_cr[EHALF];    // user-side CSR slots: {col, reverse slot}
__device__ int    g_rowptr[NN + 1];
__device__ int    g_deg[NN];
__device__ int    g_bsum[128];

// ---------------- CSR build ----------------

__global__ void k_hist(const int* __restrict__ src, int E) {
    for (int e = blockIdx.x * blockDim.x + threadIdx.x; e < E;
         e += gridDim.x * blockDim.x)
        atomicAdd(&g_deg[src[e]], 1);
}

__global__ void k_scanA() {
    __shared__ int wsum[32];
    int i = blockIdx.x * 1024 + threadIdx.x;
    int lane = threadIdx.x & 31, wid = threadIdx.x >> 5;
    int v = (i < NN) ? g_deg[i] : 0;
    int x = v;
    #pragma unroll
    for (int o = 1; o < 32; o <<= 1) {
        int y = __shfl_up_sync(0xffffffffu, x, o);
        if (lane >= o) x += y;
    }
    if (lane == 31) wsum[wid] = x;
    __syncthreads();
    if (wid == 0) {
        int s = wsum[lane];
        #pragma unroll
        for (int o = 1; o < 32; o <<= 1) {
            int y = __shfl_up_sync(0xffffffffu, s, o);
            if (lane >= o) s += y;
        }
        wsum[lane] = s;
    }
    __syncthreads();
    int woff = (wid > 0) ? wsum[wid - 1] : 0;
    int incl = x + woff;
    if (i < NN) g_rowptr[i] = incl - v;  // exclusive, local to block
    if (threadIdx.x == 1023) g_bsum[blockIdx.x] = incl;
}

__global__ void k_scanB(int nb) {
    int i = threadIdx.x;
    int v = (i < nb) ? g_bsum[i] : 0;
    int x = v;
    #pragma unroll
    for (int o = 1; o < 32; o <<= 1) {
        int y = __shfl_up_sync(0xffffffffu, x, o);
        if ((i & 31) >= o) x += y;
    }
    __shared__ int ws[4];
    if ((i & 31) == 31) ws[i >> 5] = x;
    __syncthreads();
    int off = 0;
    for (int w = 0; w < (i >> 5); w++) off += ws[w];
    if (i < nb) g_bsum[i] = x - v + off;  // exclusive
}

__global__ void k_scanC(int E) {
    int i = blockIdx.x * 1024 + threadIdx.x;
    if (i < NN) {
        g_rowptr[i] += g_bsum[blockIdx.x];
        g_deg[i] = 0;  // reset as scatter cursor
    }
    if (i == 0) g_rowptr[NN] = E;
}

// scatter BOTH directions of each undirected edge; record reverse-slot mapping.
// src = [u..., i...], dst = [i..., u...]; pair e is (src[e], src[e+EH]).
__global__ void k_scatter(const int* __restrict__ src, const float* __restrict__ adj,
                          int EH) {
    for (int e = blockIdx.x * blockDim.x + threadIdx.x; e < EH;
         e += gridDim.x * blockDim.x) {
        int u = src[e];
        int i = src[e + EH];
        float a = adj[e];
        int pos1 = g_rowptr[u] + atomicAdd(&g_deg[u], 1);
        int pos2 = g_rowptr[i] + atomicAdd(&g_deg[i], 1);
        g_edge[pos1] = make_float4(__int_as_float(i), 0.f, a, a);
        g_edge[pos2] = make_float4(__int_as_float(u), 0.f, a, a);
        g_cr[pos1]   = make_int2(i, pos2);   // user rows occupy slots [0, EH)
    }
}

// ---------------- init embeddings + light + layer-0 rnorm (fused) ----------------

__global__ void k_init(const float* __restrict__ ue, const float* __restrict__ ie) {
    int row = blockIdx.x * (blockDim.x >> 5) + (threadIdx.x >> 5);
    if (row >= NN) return;
    int lane = threadIdx.x & 31;
    const float* srcp = (row < N_USER) ? (ue + row * D) : (ie + (row - N_USER) * D);
    float2 v = *(const float2*)(srcp + lane * 2);
    *(float2*)(g_embA + row * D + lane * 2)  = v;
    *(float2*)(g_light + row * D + lane * 2) = v;
    float s = v.x * v.x + v.y * v.y;
    #pragma unroll
    for (int o = 16; o; o >>= 1) s += __shfl_xor_sync(0xffffffffu, s, o);
    if (lane == 0) g_rnorm[row] = (s > 1e-24f) ? rsqrtf(s) : 0.f;
}

// ---------------- per-layer edge passes ----------------
// k_cos: USER rows only (cos is symmetric; scatter to the reverse slot too).
// Warp per row; 4 edge-groups of 8 lanes; each lane holds 8 dims (2x float4).

__global__ __launch_bounds__(256) void k_cos(int cur) {
    const float* __restrict__ emb = cur ? g_embB : g_embA;
    int row = blockIdx.x * 8 + (threadIdx.x >> 5);
    if (row >= N_USER) return;
    int lane = threadIdx.x & 31;
    int g = lane >> 3, sl = lane & 7;

    const float* rp = emb + row * D + sl * 8;
    float4 e0 = *(const float4*)(rp);
    float4 e1 = *(const float4*)(rp + 4);
    float rn_r = g_rnorm[row];

    int beg = g_rowptr[row], end = g_rowptr[row + 1];
    int nit = (end - beg + 3) >> 2;

    // prefetch first {col, rev} for this group
    int pos = beg + g;
    bool actn = pos < end;
    int2 crn = actn ? g_cr[pos] : make_int2(0, 0);

    float rs = 0.f;
    for (int it = 0; it < nit; it++) {
        bool act = actn;
        int2 cr = crn;
        int curpos = pos;
        pos += 4;
        actn = pos < end;
        if (actn) crn = g_cr[pos];        // prefetch next iteration

        float p = 0.f;
        float rn_c = 0.f;
        if (act) {
            const float* cp = emb + cr.x * D + sl * 8;
            float4 d0 = *(const float4*)(cp);
            float4 d1 = *(const float4*)(cp + 4);
            rn_c = g_rnorm[cr.x];
            p = e0.x * d0.x + e0.y * d0.y + e0.z * d0.z + e0.w * d0.w
              + e1.x * d1.x + e1.y * d1.y + e1.z * d1.z + e1.w * d1.w;
        }
        p += __shfl_xor_sync(0xffffffffu, p, 1);
        p += __shfl_xor_sync(0xffffffffu, p, 2);
        p += __shfl_xor_sync(0xffffffffu, p, 4);
        float cs = p * rn_r * rn_c;        // 0 for inactive (rn_c = 0)
        if (act && sl == 0) {
            ((float*)(g_edge + curpos))[1] = cs;   // user-side slot
            ((float*)(g_edge + cr.y))[1]   = cs;   // item-side (reverse) slot
        }
        rs += fabsf(cs);
    }
    // rs identical across the 8 lanes of a group; combine the 4 groups
    rs += __shfl_xor_sync(0xffffffffu, rs, 8);
    rs += __shfl_xor_sync(0xffffffffu, rs, 16);
    if (lane == 0) g_rowsum[row] = (rs > 0.f) ? 1.f / rs : 1.f;
}

// item-row reciprocal L1 rowsums from the already-written cos values (scalar reads)
__global__ __launch_bounds__(256) void k_rowsum_it() {
    int row = N_USER + blockIdx.x * 8 + (threadIdx.x >> 5);
    if (row >= NN) return;
    int lane = threadIdx.x & 31;
    int beg = g_rowptr[row], end = g_rowptr[row + 1];
    float rs = 0.f;
    for (int pos = beg + lane; pos < end; pos += 32)
        rs += fabsf(((const float*)(g_edge + pos))[1]);
    #pragma unroll
    for (int o = 16; o; o >>= 1) rs += __shfl_xor_sync(0xffffffffu, rs, o);
    if (lane == 0) g_rowsum[row] = (rs > 0.f) ? 1.f / rs : 1.f;
}

// coef -> prune -> mem EMA -> SpMM row accumulate (+ light sum, + next rnorm)
__global__ __launch_bounds__(256) void k_spmm(int cur, int last,
                                              const float* __restrict__ W,
                                              const float* __restrict__ B) {
    const float* __restrict__ embin = cur ? g_embB : g_embA;
    float* embout                   = cur ? g_embA : g_embB;
    int row = blockIdx.x * 8 + (threadIdx.x >> 5);
    if (row >= NN) return;
    int lane = threadIdx.x & 31;
    int g = lane >> 3, sl = lane & 7;

    float w0 = W[0], w1 = W[1], bb = B[0];
    float invr = g_rowsum[row];   // already reciprocal
    int beg = g_rowptr[row], end = g_rowptr[row + 1];
    int nit = (end - beg + 3) >> 2;

    // prefetch first edge record
    int pos = beg + g;
    bool actn = pos < end;
    float4 en = actn ? g_edge[pos] : make_float4(0, 0, 0, 0);

    float a0 = 0.f, a1 = 0.f, a2 = 0.f, a3 = 0.f;
    float a4 = 0.f, a5 = 0.f, a6 = 0.f, a7 = 0.f;
    for (int it = 0; it < nit; it++) {
        bool act = actn;
        float4 er = en;
        int curpos = pos;
        pos += 4;
        actn = pos < end;
        if (actn) en = g_edge[pos];       // prefetch next edge record

        if (act) {
            int c = __float_as_int(er.x);
            float cs = er.y;
            float c1 = cs * invr;
            float c2 = cs * g_rowsum[c];           // cos symmetric: coef[rev] = cs / rowsum[dst]
            float z = w0 * c1 + w1 * c2 + bb;      // sigmoid(z)>0.5 <=> z>0
            float coef = (z > 0.f) ? c1 : 0.f;
            float m = 0.5f * (er.z + coef);
            if (!last && sl == 0) ((float*)(g_edge + curpos))[2] = m;
            float gv = m * er.w;
            const float* cp = embin + c * D + sl * 8;
            float4 d0 = *(const float4*)(cp);
            float4 d1 = *(const float4*)(cp + 4);
            a0 += gv * d0.x; a1 += gv * d0.y; a2 += gv * d0.z; a3 += gv * d0.w;
            a4 += gv * d1.x; a5 += gv * d1.y; a6 += gv * d1.z; a7 += gv * d1.w;
        }
    }
    // combine the 4 groups (same dims live in lanes sl, sl+8, sl+16, sl+24)
    #pragma unroll
    for (int o = 8; o <= 16; o <<= 1) {
        a0 += __shfl_xor_sync(0xffffffffu, a0, o);
        a1 += __shfl_xor_sync(0xffffffffu, a1, o);
        a2 += __shfl_xor_sync(0xffffffffu, a2, o);
        a3 += __shfl_xor_sync(0xffffffffu, a3, o);
        a4 += __shfl_xor_sync(0xffffffffu, a4, o);
        a5 += __shfl_xor_sync(0xffffffffu, a5, o);
        a6 += __shfl_xor_sync(0xffffffffu, a6, o);
        a7 += __shfl_xor_sync(0xffffffffu, a7, o);
    }
    if (g == 0) {
        float* lp = g_light + row * D + sl * 8;
        float4 l0 = *(float4*)(lp);
        float4 l1 = *(float4*)(lp + 4);
        l0.x += a0; l0.y += a1; l0.z += a2; l0.w += a3;
        l1.x += a4; l1.y += a5; l1.z += a6; l1.w += a7;
        *(float4*)(lp)     = l0;
        *(float4*)(lp + 4) = l1;
    }
    if (!last) {
        // fused reciprocal norm of the output row (input of next layer's cos)
        float ss = a0 * a0 + a1 * a1 + a2 * a2 + a3 * a3
                 + a4 * a4 + a5 * a5 + a6 * a6 + a7 * a7;
        ss += __shfl_xor_sync(0xffffffffu, ss, 1);
        ss += __shfl_xor_sync(0xffffffffu, ss, 2);
        ss += __shfl_xor_sync(0xffffffffu, ss, 4);
        if (g == 0) {
            float* op = embout + row * D + sl * 8;
            *(float4*)(op)     = make_float4(a0, a1, a2, a3);
            *(float4*)(op + 4) = make_float4(a4, a5, a6, a7);
            if (sl == 0) g_rnorm[row] = (ss > 1e-24f) ? rsqrtf(ss) : 0.f;
        }
    }
}

// ---------------- final: fused gather + sigmoid GEMM ----------------

__global__ void k_gemm(const int* __restrict__ users, const int* __restrict__ items,
                       float* __restrict__ out, int Bu, int Bi) {
    __shared__ float As[64][65];
    __shared__ float Bs[64][65];
    int tx = threadIdx.x, ty = threadIdx.y;       // 16x16
    int t = ty * 16 + tx;
    int rowBase = blockIdx.y * 64, colBase = blockIdx.x * 64;
    #pragma unroll
    for (int i = 0; i < 4; i++) {
        int j = t + i * 256;       // float4 slot 0..1023
        int r = j >> 4;
        int kq = (j & 15) * 4;
        float4 a = make_float4(0, 0, 0, 0);
        if (rowBase + r < Bu) {
            int u = users[rowBase + r];
            float4 v = *(const float4*)(g_light + u * D + kq);
            a = make_float4(0.25f * v.x, 0.25f * v.y, 0.25f * v.z, 0.25f * v.w);
        }
        As[r][kq] = a.x; As[r][kq + 1] = a.y; As[r][kq + 2] = a.z; As[r][kq + 3] = a.w;
        float4 b = make_float4(0, 0, 0, 0);
        if (colBase + r < Bi) {
            int itm = items[colBase + r];
            float4 v = *(const float4*)(g_light + (N_USER + itm) * D + kq);
            b = make_float4(0.25f * v.x, 0.25f * v.y, 0.25f * v.z, 0.25f * v.w);
        }
        Bs[r][kq] = b.x; Bs[r][kq + 1] = b.y; Bs[r][kq + 2] = b.z; Bs[r][kq + 3] = b.w;
    }
    __syncthreads();
    float acc[4][4] = {};
    #pragma unroll
    for (int k = 0; k < 64; k++) {
        float a0 = As[ty * 4 + 0][k], a1 = As[ty * 4 + 1][k];
        float a2 = As[ty * 4 + 2][k], a3 = As[ty * 4 + 3][k];
        float b0 = Bs[tx * 4 + 0][k], b1 = Bs[tx * 4 + 1][k];
        float b2 = Bs[tx * 4 + 2][k], b3 = Bs[tx * 4 + 3][k];
        acc[0][0] += a0 * b0; acc[0][1] += a0 * b1; acc[0][2] += a0 * b2; acc[0][3] += a0 * b3;
        acc[1][0] += a1 * b0; acc[1][1] += a1 * b1; acc[1][2] += a1 * b2; acc[1][3] += a1 * b3;
        acc[2][0] += a2 * b0; acc[2][1] += a2 * b1; acc[2][2] += a2 * b2; acc[2][3] += a2 * b3;
        acc[3][0] += a3 * b0; acc[3][1] += a3 * b1; acc[3][2] += a3 * b2; acc[3][3] += a3 * b3;
    }
    #pragma unroll
    for (int i = 0; i < 4; i++)
        #pragma unroll
        for (int j = 0; j < 4; j++) {
            int r = rowBase + ty * 4 + i;
            int c = colBase + tx * 4 + j;
            if (r < Bu && c < Bi)
                out[r * Bi + c] = 1.f / (1.f + __expf(-acc[i][j]));
        }
}

// ---------------- launch ----------------

extern "C" void kernel_launch(void* const* d_in, const int* in_sizes, int n_in,
                              void* d_out, int out_size) {
    const int*   users    = (const int*)d_in[0];
    const int*   items    = (const int*)d_in[1];
    const float* user_emb = (const float*)d_in[2];
    const float* item_emb = (const float*)d_in[3];
    const float* W_prune  = (const float*)d_in[4];
    const float* b_prune  = (const float*)d_in[5];
    const int*   src      = (const int*)d_in[6];
    // d_in[7] = dst (second half of src mirrors it), d_in[8] = rev_perm (unused)
    const float* adj_vals = (const float*)d_in[9];

    int Bu = in_sizes[0];
    int Bi = in_sizes[1];
    int E  = in_sizes[6];
    int EH = E / 2;

    float* out = (float*)d_out;

    // zero degree counters (memset node, not a kernel)
    void* degp = nullptr;
    cudaGetSymbolAddress(&degp, g_deg);
    cudaMemsetAsync(degp, 0, NN * sizeof(int));

    // CSR build
    k_hist<<<(E + 1023) / 1024, 1024>>>(src, E);
    k_scanA<<<NB_SCAN, 1024>>>();
    k_scanB<<<1, 128>>>(NB_SCAN);
    k_scanC<<<NB_SCAN, 1024>>>(E);
    k_scatter<<<(EH + 1023) / 1024, 1024>>>(src, adj_vals, EH);

    // init embeddings + light + layer-0 reciprocal norms (fused, warp per row)
    k_init<<<(NN + 7) / 8, 256>>>(user_emb, item_emb);

    // 3 propagation layers
    int ublocks = (N_USER + 7) / 8;
    int iblocks = (N_ITEM + 7) / 8;
    int ablocks = (NN + 7) / 8;
    for (int l = 0; l < 3; l++) {
        int cur = l & 1;
        k_cos<<<ublocks, 256>>>(cur);
        k_rowsum_it<<<iblocks, 256>>>();
        k_spmm<<<ablocks, 256>>>(cur, l == 2, W_prune, b_prune);
    }

    // fused gather + sigmoid GEMM
    dim3 gblk(16, 16);
    dim3 ggrd((Bi + 63) / 64, (Bu + 63) / 64);
    k_gemm<<<ggrd, gblk>>>(users, items, out, Bu, Bi);
}